// round 11
// baseline (speedup 1.0000x reference)
#include <cuda_runtime.h>
#include <cuda_bf16.h>

// SSIM loss: X,Y (32,8,320,320) fp32, 7x7 uniform box (valid), out = 1 - mean(S)
//
// Strip-mined vertical slide + SOFTWARE-PIPELINED PREFETCH:
//  - per iteration: slide(carry+cur)->s_E, sync, LDG next rows into the
//    now-dead cur[] regs, phase2 (hides the LDG latency), sync.
//  - phase 2 ring removed: old window entry re-read from SMEM (frees 28 regs
//    so the prefetch fits without spills).
//  - paired reciprocal: 1 rcp per 2 outputs, inactive lanes masked to (0,1).

#define WIN      7
#define IMG      320
#define OUT      314
#define NIMG     256
#define NELEM    25240576.0

#define COLS     64
#define TILE_W   58
#define STRIP    80                  // output rows per block strip
#define HALF     40                  // rows per thread-segment
#define NITER    5                   // iterations of 16 buffer rows (8 per seg)
#define SSTRIDE  (COLS + 1)          // 65 float4 entries per row
#define GRID_X   6
#define GRID_Y   4
#define NBLOCKS  (GRID_X * GRID_Y * NIMG)   // 6144

__device__ double g_accum;
__device__ unsigned int g_count;

// ---- packed f32x2 helpers (sm_103a) ----
__device__ __forceinline__ float2 f2add(float2 a, float2 b) {
    unsigned long long ra = *(unsigned long long*)&a;
    unsigned long long rb = *(unsigned long long*)&b;
    unsigned long long rd;
    asm("add.rn.f32x2 %0, %1, %2;" : "=l"(rd) : "l"(ra), "l"(rb));
    return *(float2*)&rd;
}
__device__ __forceinline__ float2 f2mul(float2 a, float2 b) {
    unsigned long long ra = *(unsigned long long*)&a;
    unsigned long long rb = *(unsigned long long*)&b;
    unsigned long long rd;
    asm("mul.rn.f32x2 %0, %1, %2;" : "=l"(rd) : "l"(ra), "l"(rb));
    return *(float2*)&rd;
}
__device__ __forceinline__ float2 f2fma(float2 a, float2 b, float2 c) {
    unsigned long long ra = *(unsigned long long*)&a;
    unsigned long long rb = *(unsigned long long*)&b;
    unsigned long long rc = *(unsigned long long*)&c;
    unsigned long long rd;
    asm("fma.rn.f32x2 %0, %1, %2, %3;" : "=l"(rd) : "l"(ra), "l"(rb), "l"(rc));
    return *(float2*)&rd;
}

__global__ __launch_bounds__(128, 8) void ssim_main_kernel(
    const float* __restrict__ X, const float* __restrict__ Y,
    const float* __restrict__ data_range, const float* __restrict__ w,
    float* __restrict__ out)
{
    __shared__ float4 s_E[16][SSTRIDE];   // (sx, sy, sxx+syy, sxy)
    __shared__ float  warpsum[4];

    const int img = blockIdx.z;
    const int tx0 = blockIdx.x * TILE_W;
    const int ty0 = blockIdx.y * STRIP;
    const float* Xb = X + (size_t)img * IMG * IMG;
    const float* Yb = Y + (size_t)img * IMG * IMG;
    const int tid = threadIdx.x;
    const float2 neg1 = make_float2(-1.f, -1.f);

    // constants for SSIM (rescaled by (1/w)^2)
    const float w0  = w[0];
    const float iw  = 1.0f / w0;                // ~49
    const float dr  = data_range[0];
    const float c1t = 0.01f * dr;
    const float c2t = 0.03f * dr;
    const float C1s = (c1t * c1t) * iw * iw;
    const float C2s = (c2t * c2t) * iw * iw;
    const float COV  = 49.0f / 48.0f;
    const float COV2 = 2.0f * COV;
    const float epsS = 1e-8f * (iw * iw) * (iw * iw);

    // phase-1 coords: thread = (column, segment)
    const int col = tid & (COLS - 1);
    const int seg = tid >> 6;                   // 0..1
    const int gx  = min(tx0 + col, IMG - 1);    // clamped cols feed only
                                                // discarded outputs
    const int base = ty0 + seg * HALF;          // first input row of segment
    const float* xp = Xb + (size_t)base * IMG + gx;
    const float* yp = Yb + (size_t)base * IMG + gx;

    // phase-2 coords
    const int r2 = tid & 15;                    // buffer row
    const int q  = tid >> 4;                    // 0..7 column chunk
    const int c0 = q * 8;

    // prime carry: input rows base..base+5 (max base=280 -> always in-bounds)
    float cx[6], cy[6];
    #pragma unroll
    for (int j = 0; j < 6; j++) {
        cx[j] = __ldg(xp + j * IMG);
        cy[j] = __ldg(yp + j * IMG);
    }
    // prime cur: input rows base+6..base+13 (max 293 -> in-bounds)
    float nx[8], ny[8];
    #pragma unroll
    for (int j = 0; j < 8; j++) {
        nx[j] = __ldg(xp + (6 + j) * IMG);
        ny[j] = __ldg(yp + (6 + j) * IMG);
    }

    float local = 0.f;

    #pragma unroll 1
    for (int it = 0; it < NITER; ++it) {
        // ---- vertical slide over 14-row window (carry[6] + cur[8]) ----
        {
            float2 P = make_float2(0.f, 0.f);
            float2 Q = make_float2(0.f, 0.f);
            float  R = 0.f;
            // window rows 0..6 = carry[0..5], cur[0]
            #pragma unroll
            for (int k = 0; k < 6; k++) {
                const float2 p = make_float2(cx[k], cy[k]);
                P = f2add(P, p);
                Q = f2fma(p, p, Q);
                R = fmaf(cx[k], cy[k], R);
            }
            {
                const float2 p = make_float2(nx[0], ny[0]);
                P = f2add(P, p);
                Q = f2fma(p, p, Q);
                R = fmaf(nx[0], ny[0], R);
            }
            const int rb = seg * 8;
            s_E[rb][col] = make_float4(P.x, P.y, Q.x + Q.y, R);

            #pragma unroll
            for (int r = 1; r < 8; r++) {
                const float2 pn = make_float2(nx[r], ny[r]);
                const float2 po = (r < 7) ? make_float2(cx[r - 1], cy[r - 1])
                                          : make_float2(nx[0], ny[0]);
                P = f2add(P, pn);
                P = f2fma(po, neg1, P);
                Q = f2fma(pn, pn, Q);
                const float2 mpo = f2mul(po, neg1);
                Q = f2fma(mpo, po, Q);
                R = fmaf(pn.x, pn.y, R);
                R = fmaf(-po.x, po.y, R);
                s_E[rb + r][col] = make_float4(P.x, P.y, Q.x + Q.y, R);
            }
        }
        // carry = cur[2..7]
        #pragma unroll
        for (int j = 0; j < 6; j++) { cx[j] = nx[j + 2]; cy[j] = ny[j + 2]; }

        __syncthreads();   // publish s_E

        // ---- prefetch next iteration's 8 rows into (now dead) cur regs ----
        if (it < NITER - 1) {
            const int rbase = base + (it + 1) * 8 + 6;
            const float* xpn = xp + (size_t)((it + 1) * 8 + 6) * IMG;
            const float* ypn = yp + (size_t)((it + 1) * 8 + 6) * IMG;
            if (rbase + 7 < IMG) {              // warp-uniform branch
                #pragma unroll
                for (int j = 0; j < 8; j++) {
                    nx[j] = __ldg(xpn + j * IMG);
                    ny[j] = __ldg(ypn + j * IMG);
                }
            } else {                            // only strip 3 / seg 1 tail
                #pragma unroll
                for (int j = 0; j < 8; j++) {
                    const int dj = min(rbase + j, IMG - 1) - rbase;
                    nx[j] = __ldg(xpn + dj * IMG);
                    ny[j] = __ldg(ypn + dj * IMG);
                }
            }
        }

        // ---- phase 2: horizontal sliding + SSIM on 16 buffer rows ----
        {
            const int gy = ty0 + ((r2 < 8) ? (it * 8 + r2)
                                           : (HALF + it * 8 + (r2 - 8)));
            const bool rowok = (gy < OUT);

            float2 Sp = make_float2(0.f, 0.f);
            float2 Sq = make_float2(0.f, 0.f);
            #pragma unroll
            for (int k = 0; k < WIN; k++) {
                const float4 e = s_E[r2][c0 + k];
                Sp = f2add(Sp, make_float2(e.x, e.y));
                Sq = f2add(Sq, make_float2(e.z, e.w));
            }

            float na = 0.f, da = 1.f;
            #pragma unroll
            for (int ci = 0; ci < 8; ci++) {
                const int c = c0 + ci;
                const bool active = rowok && (c < TILE_W) && (tx0 + c < OUT);

                const float sx = Sp.x, sy = Sp.y;
                const float sqq = Sq.x, sxy = Sq.y;
                const float2 PP = f2mul(Sp, Sp);
                const float t1 = sx * sy;
                const float b1 = PP.x + PP.y;
                const float A1 = fmaf(t1, 2.0f, C1s);
                const float B1 = b1 + C1s;
                const float A2 = fmaf(COV2, fmaf(iw, sxy, -t1), C2s);
                const float B2 = fmaf(COV,  fmaf(iw, sqq, -b1), C2s);
                const float nm = active ? (A1 * A2) : 0.0f;
                const float dm = active ? fmaf(B1, B2, epsS) : 1.0f;
                if (ci & 1) {
                    // one reciprocal per output pair
                    local += __fdividef(fmaf(na, dm, nm * da), da * dm);
                } else {
                    na = nm; da = dm;
                }

                if (ci < 7 && c + 7 < COLS) {
                    const float4 ne = s_E[r2][c + 7];
                    const float4 oe = s_E[r2][c];      // reload old (no ring)
                    Sp = f2add(Sp, make_float2(ne.x, ne.y));
                    Sp = f2fma(make_float2(oe.x, oe.y), neg1, Sp);
                    Sq = f2add(Sq, make_float2(ne.z, ne.w));
                    Sq = f2fma(make_float2(oe.z, oe.w), neg1, Sq);
                }
            }
        }
        __syncthreads();   // protect s_E before next iteration's writes
    }

    // ---------------- Block reduction + fused finalize ----------------------
    #pragma unroll
    for (int off = 16; off > 0; off >>= 1)
        local += __shfl_down_sync(0xffffffffu, local, off);
    if ((tid & 31) == 0) warpsum[tid >> 5] = local;
    __syncthreads();
    if (tid == 0) {
        const float v = warpsum[0] + warpsum[1] + warpsum[2] + warpsum[3];
        atomicAdd(&g_accum, (double)v);
        __threadfence();
        const unsigned done = atomicAdd(&g_count, 1u);
        if (done == NBLOCKS - 1) {
            const double total = atomicAdd(&g_accum, 0.0);
            out[0] = (float)(1.0 - total / NELEM);
            g_accum = 0.0;            // reset for next graph replay
            g_count = 0u;
        }
    }
}

extern "C" void kernel_launch(void* const* d_in, const int* in_sizes, int n_in,
                              void* d_out, int out_size) {
    const float* X  = (const float*)d_in[0];
    const float* Y  = (const float*)d_in[1];
    const float* dr = (const float*)d_in[2];
    const float* w  = (const float*)d_in[3];
    float* out = (float*)d_out;

    dim3 grid(GRID_X, GRID_Y, NIMG);
    ssim_main_kernel<<<grid, 128>>>(X, Y, dr, w, out);
}

// round 12
// speedup vs baseline: 1.2241x; 1.2241x over previous
#include <cuda_runtime.h>
#include <cuda_bf16.h>

// SSIM loss: X,Y (32,8,320,320) fp32, 7x7 uniform box (valid), out = 1 - mean(S)
//
// Strip-mined vertical slide (R10 structure) tuned for OCCUPANCY:
//  - phase-2 ring removed (old window entry re-read from SMEM) -> peak
//    liveness ~48 regs -> launch_bounds(128,10) -> ~62% occupancy (was 46%)
//  - NO prefetch (R11 lesson: cross-phase liveness at the reg cap spills)
//  - paired reciprocal: one MUFU rcp per 2 outputs (intra-loop liveness only)

#define WIN      7
#define IMG      320
#define OUT      314
#define NIMG     256
#define NELEM    25240576.0

#define COLS     64
#define TILE_W   58
#define STRIP    80                  // output rows per block strip
#define HALF     40                  // rows per thread-segment
#define NITER    5                   // iterations of 16 buffer rows (8 per seg)
#define SSTRIDE  (COLS + 1)          // 65 float4 entries per row
#define GRID_X   6
#define GRID_Y   4
#define NBLOCKS  (GRID_X * GRID_Y * NIMG)   // 6144

__device__ double g_accum;
__device__ unsigned int g_count;

// ---- packed f32x2 helpers (sm_103a) ----
__device__ __forceinline__ float2 f2add(float2 a, float2 b) {
    unsigned long long ra = *(unsigned long long*)&a;
    unsigned long long rb = *(unsigned long long*)&b;
    unsigned long long rd;
    asm("add.rn.f32x2 %0, %1, %2;" : "=l"(rd) : "l"(ra), "l"(rb));
    return *(float2*)&rd;
}
__device__ __forceinline__ float2 f2mul(float2 a, float2 b) {
    unsigned long long ra = *(unsigned long long*)&a;
    unsigned long long rb = *(unsigned long long*)&b;
    unsigned long long rd;
    asm("mul.rn.f32x2 %0, %1, %2;" : "=l"(rd) : "l"(ra), "l"(rb));
    return *(float2*)&rd;
}
__device__ __forceinline__ float2 f2fma(float2 a, float2 b, float2 c) {
    unsigned long long ra = *(unsigned long long*)&a;
    unsigned long long rb = *(unsigned long long*)&b;
    unsigned long long rc = *(unsigned long long*)&c;
    unsigned long long rd;
    asm("fma.rn.f32x2 %0, %1, %2, %3;" : "=l"(rd) : "l"(ra), "l"(rb), "l"(rc));
    return *(float2*)&rd;
}

__global__ __launch_bounds__(128, 10) void ssim_main_kernel(
    const float* __restrict__ X, const float* __restrict__ Y,
    const float* __restrict__ data_range, const float* __restrict__ w,
    float* __restrict__ out)
{
    __shared__ float4 s_E[16][SSTRIDE];   // (sx, sy, sxx+syy, sxy)
    __shared__ float  warpsum[4];

    const int img = blockIdx.z;
    const int tx0 = blockIdx.x * TILE_W;
    const int ty0 = blockIdx.y * STRIP;
    const float* Xb = X + (size_t)img * IMG * IMG;
    const float* Yb = Y + (size_t)img * IMG * IMG;
    const int tid = threadIdx.x;
    const float2 neg1 = make_float2(-1.f, -1.f);

    // constants for SSIM (rescaled by (1/w)^2)
    const float w0  = w[0];
    const float iw  = 1.0f / w0;                // ~49
    const float dr  = data_range[0];
    const float c1t = 0.01f * dr;
    const float c2t = 0.03f * dr;
    const float C1s = (c1t * c1t) * iw * iw;
    const float C2s = (c2t * c2t) * iw * iw;
    const float COV  = 49.0f / 48.0f;
    const float COV2 = 2.0f * COV;
    const float epsS = 1e-8f * (iw * iw) * (iw * iw);

    // phase-1 coords: thread = (column, segment)
    const int col = tid & (COLS - 1);
    const int seg = tid >> 6;                   // 0..1
    const int gx  = min(tx0 + col, IMG - 1);    // clamped cols feed only
                                                // discarded outputs
    const int base = ty0 + seg * HALF;          // first input row of segment
    const float* xp = Xb + (size_t)base * IMG + gx;
    const float* yp = Yb + (size_t)base * IMG + gx;

    // phase-2 coords
    const int r2 = tid & 15;                    // buffer row
    const int q  = tid >> 4;                    // 0..7 column chunk
    const int c0 = q * 8;

    // prime carry: input rows base..base+5 (max base=280 -> always in-bounds)
    float cx[6], cy[6];
    #pragma unroll
    for (int j = 0; j < 6; j++) {
        cx[j] = __ldg(xp + j * IMG);
        cy[j] = __ldg(yp + j * IMG);
    }
    const float* xp2 = xp + 6 * IMG;
    const float* yp2 = yp + 6 * IMG;

    float local = 0.f;

    #pragma unroll 1
    for (int it = 0; it < NITER; ++it) {
        // ---- load 8 new input rows (front-batched for MLP) ----
        float nx[8], ny[8];
        const int rbase = base + it * 8 + 6;
        if (rbase + 7 < IMG) {                  // warp-uniform branch
            #pragma unroll
            for (int j = 0; j < 8; j++) {
                nx[j] = __ldg(xp2 + j * IMG);
                ny[j] = __ldg(yp2 + j * IMG);
            }
        } else {                                // only strip 3 / seg 1 / it 4
            #pragma unroll
            for (int j = 0; j < 8; j++) {
                const int dj = min(rbase + j, IMG - 1) - rbase;
                nx[j] = __ldg(xp2 + dj * IMG);
                ny[j] = __ldg(yp2 + dj * IMG);
            }
        }
        xp2 += 8 * IMG; yp2 += 8 * IMG;

        // ---- vertical slide over 14-row window (carry[6] + new[8]) ----
        {
            float2 P = make_float2(0.f, 0.f);
            float2 Q = make_float2(0.f, 0.f);
            float  R = 0.f;
            #pragma unroll
            for (int k = 0; k < 6; k++) {
                const float2 p = make_float2(cx[k], cy[k]);
                P = f2add(P, p);
                Q = f2fma(p, p, Q);
                R = fmaf(cx[k], cy[k], R);
            }
            {
                const float2 p = make_float2(nx[0], ny[0]);
                P = f2add(P, p);
                Q = f2fma(p, p, Q);
                R = fmaf(nx[0], ny[0], R);
            }
            const int rb = seg * 8;
            s_E[rb][col] = make_float4(P.x, P.y, Q.x + Q.y, R);

            #pragma unroll
            for (int r = 1; r < 8; r++) {
                const float2 pn = make_float2(nx[r], ny[r]);
                const float2 po = (r < 7) ? make_float2(cx[r - 1], cy[r - 1])
                                          : make_float2(nx[0], ny[0]);
                P = f2add(P, pn);
                P = f2fma(po, neg1, P);
                Q = f2fma(pn, pn, Q);
                const float2 mpo = f2mul(po, neg1);
                Q = f2fma(mpo, po, Q);
                R = fmaf(pn.x, pn.y, R);
                R = fmaf(-po.x, po.y, R);
                s_E[rb + r][col] = make_float4(P.x, P.y, Q.x + Q.y, R);
            }
        }
        // carry = new[2..7]
        #pragma unroll
        for (int j = 0; j < 6; j++) { cx[j] = nx[j + 2]; cy[j] = ny[j + 2]; }

        __syncthreads();   // publish s_E

        // ---- phase 2: horizontal sliding + SSIM on 16 buffer rows ----
        {
            const int gy = ty0 + ((r2 < 8) ? (it * 8 + r2)
                                           : (HALF + it * 8 + (r2 - 8)));
            const bool rowok = (gy < OUT);

            float2 Sp = make_float2(0.f, 0.f);
            float2 Sq = make_float2(0.f, 0.f);
            #pragma unroll
            for (int k = 0; k < WIN; k++) {
                const float4 e = s_E[r2][c0 + k];
                Sp = f2add(Sp, make_float2(e.x, e.y));
                Sq = f2add(Sq, make_float2(e.z, e.w));
            }

            float na = 0.f, da = 1.f;
            #pragma unroll
            for (int ci = 0; ci < 8; ci++) {
                const int c = c0 + ci;
                const bool active = rowok && (c < TILE_W) && (tx0 + c < OUT);

                const float sx = Sp.x, sy = Sp.y;
                const float sqq = Sq.x, sxy = Sq.y;
                const float2 PP = f2mul(Sp, Sp);
                const float t1 = sx * sy;
                const float b1 = PP.x + PP.y;
                const float A1 = fmaf(t1, 2.0f, C1s);
                const float B1 = b1 + C1s;
                const float A2 = fmaf(COV2, fmaf(iw, sxy, -t1), C2s);
                const float B2 = fmaf(COV,  fmaf(iw, sqq, -b1), C2s);
                const float nm = active ? (A1 * A2) : 0.0f;
                const float dm = active ? fmaf(B1, B2, epsS) : 1.0f;
                if (ci & 1) {
                    // one reciprocal per output pair
                    local += __fdividef(fmaf(na, dm, nm * da), da * dm);
                } else {
                    na = nm; da = dm;
                }

                if (ci < 7 && c + 7 < COLS) {
                    const float4 ne = s_E[r2][c + 7];
                    const float4 oe = s_E[r2][c];      // reload old (no ring)
                    Sp = f2add(Sp, make_float2(ne.x, ne.y));
                    Sp = f2fma(make_float2(oe.x, oe.y), neg1, Sp);
                    Sq = f2add(Sq, make_float2(ne.z, ne.w));
                    Sq = f2fma(make_float2(oe.z, oe.w), neg1, Sq);
                }
            }
        }
        __syncthreads();   // protect s_E before next iteration's writes
    }

    // ---------------- Block reduction + fused finalize ----------------------
    #pragma unroll
    for (int off = 16; off > 0; off >>= 1)
        local += __shfl_down_sync(0xffffffffu, local, off);
    if ((tid & 31) == 0) warpsum[tid >> 5] = local;
    __syncthreads();
    if (tid == 0) {
        const float v = warpsum[0] + warpsum[1] + warpsum[2] + warpsum[3];
        atomicAdd(&g_accum, (double)v);
        __threadfence();
        const unsigned done = atomicAdd(&g_count, 1u);
        if (done == NBLOCKS - 1) {
            const double total = atomicAdd(&g_accum, 0.0);
            out[0] = (float)(1.0 - total / NELEM);
            g_accum = 0.0;            // reset for next graph replay
            g_count = 0u;
        }
    }
}

extern "C" void kernel_launch(void* const* d_in, const int* in_sizes, int n_in,
                              void* d_out, int out_size) {
    const float* X  = (const float*)d_in[0];
    const float* Y  = (const float*)d_in[1];
    const float* dr = (const float*)d_in[2];
    const float* w  = (const float*)d_in[3];
    float* out = (float*)d_out;

    dim3 grid(GRID_X, GRID_Y, NIMG);
    ssim_main_kernel<<<grid, 128>>>(X, Y, dr, w, out);
}